// round 1
// baseline (speedup 1.0000x reference)
#include <cuda_runtime.h>
#include <cstdint>

#define B_  512
#define L_  1024
#define K_  8
#define NR_ 512
#define S_  20
#define EXT_ 26
#define SQN 6
#define LT  128   // l-positions per writer block

// Scratch (device globals; no allocation allowed)
__device__ __align__(16) float g_Q[K_ * S_ * S_];                 // 12.8 KB
__device__ __align__(16) float g_P[(size_t)NR_ * K_ * S_ * S_];  // 6.55 MB
__device__ unsigned int g_used[NR_];

__device__ __forceinline__ float softplus_f(float x) {
    // logaddexp(x, 0) = max(x,0) + log1p(exp(-|x|))
    return fmaxf(x, 0.0f) + log1pf(expf(-fabsf(x)));
}

// ---------------------------------------------------------------------------
// Kernel A: build Q[k] (8 blocks of 20x20 threads)
// ---------------------------------------------------------------------------
__global__ void qprep_kernel(const float* __restrict__ exch,
                             const float* __restrict__ freq) {
    const int k = blockIdx.x;
    const int i = threadIdx.y;
    const int j = threadIdx.x;

    __shared__ float Rs[S_][S_ + 1];
    __shared__ float diag[S_];
    __shared__ float fr[S_];

    if (i == 0) fr[j] = freq[j];

    float e1 = exch[(k * S_ + i) * S_ + j];
    float e2 = exch[(k * S_ + j) * S_ + i];
    float r = softplus_f(0.5f * (e1 + e2));
    if (i == j) r = 0.0f;
    __syncthreads();            // fr ready

    float q = r * fr[j];        // R * frequencies[None,None,:]
    Rs[i][j] = q;
    __syncthreads();

    if (j == 0) {
        float d = 0.0f;
        #pragma unroll
        for (int t = 0; t < S_; t++) d += Rs[i][t];
        diag[i] = d;
    }
    __syncthreads();

    float mue = 0.0f;
    #pragma unroll
    for (int t = 0; t < S_; t++) mue += fr[t] * diag[t];
    mue = fmaxf(mue, 1e-16f);

    float val = q - (i == j ? diag[i] : 0.0f);
    g_Q[(k * S_ + i) * S_ + j] = val / mue;
}

// ---------------------------------------------------------------------------
// Kernel B0/B1: mark which rate indices are actually used
// ---------------------------------------------------------------------------
__global__ void clear_used_kernel() {
    int r = blockIdx.x * blockDim.x + threadIdx.x;
    if (r < NR_) g_used[r] = 0u;
}
__global__ void mark_used_kernel(const int* __restrict__ rate_indices) {
    int b = blockIdx.x * blockDim.x + threadIdx.x;
    if (b < B_) g_used[rate_indices[b]] = 1u;
}

// ---------------------------------------------------------------------------
// Kernel C: expm of tau[r] * Q[k] for each (r,k). One 20x20 block per matrix.
// Scaling(2^-6) + order-16 Taylor + 6 squarings, matching the reference.
// ---------------------------------------------------------------------------
__global__ void expm_kernel(const float* __restrict__ tau_kernel) {
    const int m = blockIdx.x;          // r*K + k
    const int r = m / K_;
    const int k = m - r * K_;
    if (!g_used[r]) return;

    const int i = threadIdx.y;
    const int j = threadIdx.x;

    __shared__ float As[S_][S_ + 1];
    __shared__ float Ts[2][S_][S_ + 1];
    __shared__ float Ps[2][S_][S_ + 1];

    const float tau = softplus_f(tau_kernel[r]);
    float a = tau * g_Q[(k * S_ + i) * S_ + j] * (1.0f / 64.0f);

    As[i][j] = a;
    Ts[0][i][j] = a;
    float p = (i == j ? 1.0f : 0.0f) + a;   // P = I + A (register-resident)
    __syncthreads();

    int cur = 0;
    #pragma unroll 1
    for (int n = 2; n <= 16; n++) {
        float s = 0.0f;
        #pragma unroll
        for (int t = 0; t < S_; t++) s += Ts[cur][i][t] * As[t][j];
        s = s / (float)n;
        Ts[cur ^ 1][i][j] = s;
        cur ^= 1;
        p += s;
        __syncthreads();
    }

    Ps[0][i][j] = p;
    __syncthreads();
    int pc = 0;
    #pragma unroll 1
    for (int q = 0; q < SQN; q++) {
        float s = 0.0f;
        #pragma unroll
        for (int t = 0; t < S_; t++) s += Ps[pc][i][t] * Ps[pc][t][j];
        Ps[pc ^ 1][i][j] = s;
        pc ^= 1;
        __syncthreads();
    }

    g_P[(size_t)m * (S_ * S_) + i * S_ + j] = Ps[pc][i][j];
}

// ---------------------------------------------------------------------------
// Kernel D: the bandwidth kernel. One block per (b, 128-l strip).
// Loads P[r,:, :, :] (12.8 KB) to smem, emits coalesced float4 rows.
// ---------------------------------------------------------------------------
__global__ void __launch_bounds__(256) writer_kernel(
        const int* __restrict__ inputs,
        const int* __restrict__ rate_indices,
        float* __restrict__ out) {
    const int b  = blockIdx.y;
    const int l0 = blockIdx.x * LT;

    __shared__ float Pt[K_ * S_ * S_];   // 3200 floats
    __shared__ int   cs[LT];

    const int r = rate_indices[b];
    const float4* src = (const float4*)(g_P + (size_t)r * (K_ * S_ * S_));
    #pragma unroll
    for (int v = threadIdx.x; v < (K_ * S_ * S_) / 4; v += 256)
        ((float4*)Pt)[v] = src[v];
    for (int t = threadIdx.x; t < LT; t += 256)
        cs[t] = inputs[b * L_ + l0 + t];
    __syncthreads();

    const int VEC = (K_ * EXT_) / 4;     // 52 float4 per position
    float4* orow = (float4*)(out + ((size_t)b * L_ + l0) * (K_ * EXT_));

    #pragma unroll 2
    for (int v = threadIdx.x; v < LT * VEC; v += 256) {
        const int p = v / VEC;
        const int j = v - p * VEC;
        const int c = cs[p];
        const int f0 = j * 4;
        float vals[4];
        #pragma unroll
        for (int u = 0; u < 4; u++) {
            const int f  = f0 + u;
            const int kk = f / EXT_;
            const int e  = f - kk * EXT_;
            float x;
            if (c < S_) {
                x = (e < S_) ? Pt[kk * (S_ * S_) + c * S_ + e] : 0.0f;
            } else {
                x = (e == c) ? 1.0f : 0.0f;
            }
            vals[u] = x;
        }
        float4 o;
        o.x = vals[0]; o.y = vals[1]; o.z = vals[2]; o.w = vals[3];
        orow[(size_t)p * VEC + j] = o;
    }
}

// ---------------------------------------------------------------------------
extern "C" void kernel_launch(void* const* d_in, const int* in_sizes, int n_in,
                              void* d_out, int out_size) {
    const int*   inputs       = (const int*)  d_in[0];   // (B, L) int32
    const int*   rate_indices = (const int*)  d_in[1];   // (B,)   int32
    const float* tau_kernel   = (const float*)d_in[2];   // (NR,)  f32
    const float* exch         = (const float*)d_in[3];   // (K,S,S) f32
    const float* freq         = (const float*)d_in[4];   // (S,)   f32
    float*       out          = (float*)d_out;           // (B, L, K*EXT) f32

    (void)in_sizes; (void)n_in; (void)out_size;

    dim3 tb(S_, S_);  // 20x20 = 400 threads

    qprep_kernel<<<K_, tb>>>(exch, freq);
    clear_used_kernel<<<(NR_ + 255) / 256, 256>>>();
    mark_used_kernel<<<(B_ + 255) / 256, 256>>>(rate_indices);
    expm_kernel<<<NR_ * K_, tb>>>(tau_kernel);

    dim3 grid(L_ / LT, B_);
    writer_kernel<<<grid, 256>>>(inputs, rate_indices, out);
}